// round 15
// baseline (speedup 1.0000x reference)
#include <cuda_runtime.h>

#define NN 256
#define TT 1500
#define R 4
#define CT (32 * R)                  // 128 steps per warp-chunk
#define NFULL (TT / CT)              // 11 full chunks (tail: 92 steps, lanes 0..22)
#define PLANE (NN * TT)

// One cell's 128-step chunk with a DECOUPLED carry: the scan never depends on
// the previous chunk (the 32-step truncation window means the incoming carry
// only affects lanes 0..6, fixed by one post-scan fma; the outgoing carry B31
// has a fully internal window). Successive chunks are therefore independent
// instruction streams that the compiler can interleave (unroll 2).
template<bool TAIL>
__device__ __forceinline__ void cell_chunk(const float4 x, const float4 y,
                                           const bool act, const int lane,
                                           float& carry, float* __restrict__ o) {
    float a0, a1, a2, a3, A, B;
    if (!TAIL || act) {
        a0 = x.x + y.x;  a1 = x.y + y.y;  a2 = x.z + y.z;  a3 = x.w + y.w;
        A = a0; B = fmaf(-20.0f, a0, 12.5f);
        B = fmaf(a1, B, fmaf(-20.0f, a1, 12.5f)); A *= a1;
        B = fmaf(a2, B, fmaf(-20.0f, a2, 12.5f)); A *= a2;
        B = fmaf(a3, B, fmaf(-20.0f, a3, 12.5f)); A *= a3;
    } else {
        A = 1.0f; B = 0.0f;
        a0 = a1 = a2 = a3 = 1.0f;
    }

    // carry-free 3-level truncated scan (window 8 lanes = 32 steps)
    float Au, Bu;
    Au = __shfl_up_sync(0xffffffffu, A, 1);
    Bu = __shfl_up_sync(0xffffffffu, B, 1);
    if (lane >= 1) { B = fmaf(A, Bu, B); A *= Au; }
    Au = __shfl_up_sync(0xffffffffu, A, 2);
    Bu = __shfl_up_sync(0xffffffffu, B, 2);
    if (lane >= 2) { B = fmaf(A, Bu, B); A *= Au; }
    Au = __shfl_up_sync(0xffffffffu, A, 4);
    Bu = __shfl_up_sync(0xffffffffu, B, 4);
    if (lane >= 4) { B = fmaf(A, Bu, B); A *= Au; }

    // outgoing carry: independent of the incoming one (internal window)
    float cnew = __shfl_sync(0xffffffffu, B, 31);

    // apply incoming carry where the window reaches back (exact for 0..6;
    // lanes >=7 dropped terms <= 0.625^32 ~ 3e-7)
    if (lane < 7) B = fmaf(A, carry, B);

    float vs = __shfl_up_sync(0xffffffffu, B, 1);
    float v = (lane == 0) ? carry : vs;
    carry = cnew;

    if (!TAIL || act) {
        float4 r;
        v = fmaf(a0, v, fmaf(-20.0f, a0, 12.5f)); r.x = v;
        v = fmaf(a1, v, fmaf(-20.0f, a1, 12.5f)); r.y = v;
        v = fmaf(a2, v, fmaf(-20.0f, a2, 12.5f)); r.z = v;
        v = fmaf(a3, v, fmaf(-20.0f, a3, 12.5f)); r.w = v;
        __stcs((float4*)o, r);                    // streaming: never re-read
    }
}

// load u chunk -> half-coefficient q = 0.3125 - c*sat(u)
__device__ __forceinline__ float4 load_q(const float* __restrict__ base,
                                         const int t, const float c) {
    float4 x = *(const float4*)(base + t);
    float4 q;
    q.x = fmaf(-c, __saturatef(x.x), 0.3125f);
    q.y = fmaf(-c, __saturatef(x.y), 0.3125f);
    q.z = fmaf(-c, __saturatef(x.z), 0.3125f);
    q.w = fmaf(-c, __saturatef(x.w), 0.3125f);
    return q;
}

// R12 chassis: fused, 2x2 cell tile per warp, 8 explicit pointers; main loop
// unrolled 2x so two chunks' (now independent) scans interleave.
__global__ __launch_bounds__(256) void sim_kernel(
    const float* __restrict__ u0, const float* __restrict__ u1,
    const float* __restrict__ ksyn, float* __restrict__ out)
{
    const int lane = threadIdx.x & 31;
    const int w    = threadIdx.x >> 5;              // 0..7
    const int i0 = blockIdx.y * 4 + (w >> 2) * 2;
    const int j0 = blockIdx.x * 8 + (w & 3) * 2;

    const float ki0 = ksyn[i0],      ki1 = ksyn[i0 + 1];
    const float kj0 = ksyn[NN + j0], kj1 = ksyn[NN + j0 + 1];
    const float ci0 = 0.075f * ki0 / (20.0f - 2.0f * ki0);
    const float ci1 = 0.075f * ki1 / (20.0f - 2.0f * ki1);
    const float cj0 = 0.075f * kj0 / (20.0f - 2.0f * kj0);
    const float cj1 = 0.075f * kj1 / (20.0f - 2.0f * kj1);

    const float* __restrict__ xi0 = u0 + i0 * TT;
    const float* __restrict__ xi1 = xi0 + TT;
    const float* __restrict__ yj0 = u1 + j0 * TT;
    const float* __restrict__ yj1 = yj0 + TT;

    float* __restrict__ o00 = out + (i0 * NN + j0) * TT;
    float* __restrict__ o01 = o00 + TT;
    float* __restrict__ o10 = o00 + NN * TT;
    float* __restrict__ o11 = o10 + TT;

    float c00 = 0.0f, c01 = 0.0f, c10 = 0.0f, c11 = 0.0f;

    #pragma unroll 2
    for (int c = 0; c < NFULL; c++) {
        const int t = c * CT + lane * R;

        float4 qx0 = load_q(xi0, t, ci0);
        float4 qx1 = load_q(xi1, t, ci1);
        float4 qy0 = load_q(yj0, t, cj0);
        float4 qy1 = load_q(yj1, t, cj1);

        cell_chunk<false>(qx0, qy0, true, lane, c00, o00 + t);
        cell_chunk<false>(qx0, qy1, true, lane, c01, o01 + t);
        cell_chunk<false>(qx1, qy0, true, lane, c10, o10 + t);
        cell_chunk<false>(qx1, qy1, true, lane, c11, o11 + t);
    }

    // tail chunk: steps 1408..1499, lanes 0..22 active (whole float4s)
    {
        const int t = NFULL * CT + lane * R;
        const bool act = (t < TT);

        float4 qx0, qx1, qy0, qy1;
        if (act) {
            qx0 = load_q(xi0, t, ci0);
            qx1 = load_q(xi1, t, ci1);
            qy0 = load_q(yj0, t, cj0);
            qy1 = load_q(yj1, t, cj1);
        }

        cell_chunk<true>(qx0, qy0, act, lane, c00, o00 + t);
        cell_chunk<true>(qx0, qy1, act, lane, c01, o01 + t);
        cell_chunk<true>(qx1, qy0, act, lane, c10, o10 + t);
        cell_chunk<true>(qx1, qy1, act, lane, c11, o11 + t);
    }
}

extern "C" void kernel_launch(void* const* d_in, const int* in_sizes, int n_in,
                              void* d_out, int out_size) {
    const float* u0   = (const float*)d_in[0];   // u_pre_0 (N,T)
    const float* u1   = (const float*)d_in[1];   // u_pre_1 (N,T)
    const float* ksyn = (const float*)d_in[2];   // k_syn (2,N)
    float* out = (float*)d_out;                  // (N,N,T) fp32

    dim3 grid(NN / 8, NN / 4);                   // 32 x 64 = 2048 blocks
    sim_kernel<<<grid, 256>>>(u0, u1, ksyn, out);
}